// round 7
// baseline (speedup 1.0000x reference)
#include <cuda_runtime.h>
#include <math.h>

// Problem dims
#define B_DIM 8192
#define D_DIM 1024
#define H_DIM 4096
#define E_DIM 8
#define C_DIM 1024

// GEMM tiling
#define BM 128
#define BN 128
#define BK 32
#define AS_ST (BK + 4)           // 36 floats: (4*row + k) % 32 conflict-free A frag loads
#define BS_ST (BN + 8)           // 136 floats: (8*k + n) % 32 conflict-free B frag loads
#define STAGE_A (BM * AS_ST)     // 4608 floats
#define STAGE_B (BK * BS_ST)     // 4352 floats
#define SMEM_BYTES ((2 * (STAGE_A + STAGE_B)) * 4)   // 71680 bytes

// 1 GiB scratch for h = relu(x @ W1 + b1), layout [B][E][H]
__device__ float g_hbuf[268435456];  // 8192 * 8 * 4096

// ---------------------------------------------------------------------------
// helpers
// ---------------------------------------------------------------------------
__device__ __forceinline__ unsigned f2tf32(float f) {
    unsigned u;
    asm("cvt.rna.tf32.f32 %0, %1;" : "=r"(u) : "f"(f));
    return u;
}

__device__ __forceinline__ void cp_async16(const float* smem_dst, const float* gsrc) {
    unsigned s = (unsigned)__cvta_generic_to_shared((void*)smem_dst);
    asm volatile("cp.async.cg.shared.global [%0], [%1], 16;" :: "r"(s), "l"(gsrc));
}

__device__ __forceinline__ void mma_tf32(float* c, const unsigned* a, const unsigned* b) {
    asm volatile(
        "mma.sync.aligned.m16n8k8.row.col.f32.tf32.tf32.f32 "
        "{%0,%1,%2,%3}, {%4,%5,%6,%7}, {%8,%9}, {%0,%1,%2,%3};"
        : "+f"(c[0]), "+f"(c[1]), "+f"(c[2]), "+f"(c[3])
        : "r"(a[0]), "r"(a[1]), "r"(a[2]), "r"(a[3]), "r"(b[0]), "r"(b[1]));
}

// ---------------------------------------------------------------------------
// TF32 GEMM: C[m][n] = op( sum_k A[m][k]*B[k][n] + bias[n] )
// Per-expert strides applied via blockIdx.z. A,B row-major with given ld.
// ---------------------------------------------------------------------------
template <bool RELU>
__global__ void __launch_bounds__(256, 1)
gemm_tf32(const float* __restrict__ A, const float* __restrict__ B,
          const float* __restrict__ bias, float* __restrict__ C,
          int K, int lda, int ldb, int ldc,
          long sAe, long sBe, long sBiasE, long sCe)
{
    extern __shared__ float sm[];
    float* As = sm;                       // 2 stages
    float* Bs = sm + 2 * STAGE_A;

    const int e = blockIdx.z;
    A    += (long)e * sAe;
    B    += (long)e * sBe;
    bias += (long)e * sBiasE;
    C    += (long)e * sCe;

    const int m0 = blockIdx.y * BM;
    const int n0 = blockIdx.x * BN;
    const int tid  = threadIdx.x;
    const int lane = tid & 31;
    const int wid  = tid >> 5;
    const int wm0 = (wid & 1) * 64;   // 2 warps along M
    const int wn0 = (wid >> 1) * 32;  // 4 warps along N
    const int g = lane >> 2, q = lane & 3;

    float acc[4][4][4];
#pragma unroll
    for (int mt = 0; mt < 4; mt++)
#pragma unroll
        for (int nt = 0; nt < 4; nt++)
#pragma unroll
            for (int i = 0; i < 4; i++) acc[mt][nt][i] = 0.f;

    auto load_tile = [&](int kb, int s) {
        float* as = As + s * STAGE_A;
        float* bs = Bs + s * STAGE_B;
#pragma unroll
        for (int i = 0; i < 4; i++) {            // A: 128x32 floats = 1024 float4
            int lin = tid + i * 256;
            int row = lin >> 3, k4 = (lin & 7) << 2;
            cp_async16(&as[row * AS_ST + k4], &A[(long)(m0 + row) * lda + kb + k4]);
        }
#pragma unroll
        for (int i = 0; i < 4; i++) {            // B: 32x128 floats
            int lin = tid + i * 256;
            int kr = lin >> 5, n4 = (lin & 31) << 2;
            cp_async16(&bs[kr * BS_ST + n4], &B[(long)(kb + kr) * ldb + n0 + n4]);
        }
        asm volatile("cp.async.commit_group;");
    };

    auto compute = [&](int s) {
        const float* as = As + s * STAGE_A;
        const float* bs = Bs + s * STAGE_B;
#pragma unroll
        for (int kk = 0; kk < 4; kk++) {
            const int k0 = kk * 8;
            unsigned a[4][4], bf[4][2];
#pragma unroll
            for (int mt = 0; mt < 4; mt++) {
                int r = wm0 + mt * 16 + g;
                a[mt][0] = f2tf32(as[r * AS_ST + k0 + q]);
                a[mt][1] = f2tf32(as[(r + 8) * AS_ST + k0 + q]);
                a[mt][2] = f2tf32(as[r * AS_ST + k0 + q + 4]);
                a[mt][3] = f2tf32(as[(r + 8) * AS_ST + k0 + q + 4]);
            }
#pragma unroll
            for (int nt = 0; nt < 4; nt++) {
                int n = wn0 + nt * 8 + g;
                bf[nt][0] = f2tf32(bs[(k0 + q) * BS_ST + n]);
                bf[nt][1] = f2tf32(bs[(k0 + q + 4) * BS_ST + n]);
            }
#pragma unroll
            for (int mt = 0; mt < 4; mt++)
#pragma unroll
                for (int nt = 0; nt < 4; nt++)
                    mma_tf32(acc[mt][nt], a[mt], bf[nt]);
        }
    };

    const int KT = K / BK;
    load_tile(0, 0);
    for (int kt = 0; kt < KT; kt++) {
        int cur = kt & 1;
        if (kt + 1 < KT) {
            load_tile((kt + 1) * BK, cur ^ 1);
            asm volatile("cp.async.wait_group 1;");
        } else {
            asm volatile("cp.async.wait_group 0;");
        }
        __syncthreads();
        compute(cur);
        __syncthreads();
    }

    // Epilogue: + bias, optional relu, store
#pragma unroll
    for (int mt = 0; mt < 4; mt++) {
        int r = m0 + wm0 + mt * 16 + g;
#pragma unroll
        for (int nt = 0; nt < 4; nt++) {
            int c = n0 + wn0 + nt * 8 + 2 * q;
            float b0v = bias[c], b1v = bias[c + 1];
            float v00 = acc[mt][nt][0] + b0v;
            float v01 = acc[mt][nt][1] + b1v;
            float v10 = acc[mt][nt][2] + b0v;
            float v11 = acc[mt][nt][3] + b1v;
            if (RELU) {
                v00 = fmaxf(v00, 0.f); v01 = fmaxf(v01, 0.f);
                v10 = fmaxf(v10, 0.f); v11 = fmaxf(v11, 0.f);
            }
            C[(long)r * ldc + c]           = v00;
            C[(long)r * ldc + c + 1]       = v01;
            C[(long)(r + 8) * ldc + c]     = v10;
            C[(long)(r + 8) * ldc + c + 1] = v11;
        }
    }
}

// ---------------------------------------------------------------------------
// Gating: softmax(x @ Wg + bg). One warp per row (fp32 exact).
// ---------------------------------------------------------------------------
__global__ void gating_kernel(const float* __restrict__ x, const float* __restrict__ Wg,
                              const float* __restrict__ bg, float* __restrict__ gate)
{
    int warp = threadIdx.x >> 5, lane = threadIdx.x & 31;
    int b = blockIdx.x * 8 + warp;
    const float* xr = x + (long)b * D_DIM;

    float acc[8];
#pragma unroll
    for (int i = 0; i < 8; i++) acc[i] = 0.f;

    for (int d = lane; d < D_DIM; d += 32) {
        float xv = xr[d];
        const float4* w = reinterpret_cast<const float4*>(Wg + (long)d * E_DIM);
        float4 w0 = w[0], w1 = w[1];
        acc[0] += xv * w0.x; acc[1] += xv * w0.y;
        acc[2] += xv * w0.z; acc[3] += xv * w0.w;
        acc[4] += xv * w1.x; acc[5] += xv * w1.y;
        acc[6] += xv * w1.z; acc[7] += xv * w1.w;
    }
#pragma unroll
    for (int off = 16; off > 0; off >>= 1)
#pragma unroll
        for (int i = 0; i < 8; i++)
            acc[i] += __shfl_xor_sync(0xffffffffu, acc[i], off);

    if (lane == 0) {
        float m = -1e30f;
#pragma unroll
        for (int i = 0; i < 8; i++) { acc[i] += bg[i]; m = fmaxf(m, acc[i]); }
        float s = 0.f;
#pragma unroll
        for (int i = 0; i < 8; i++) { acc[i] = expf(acc[i] - m); s += acc[i]; }
        float inv = 1.f / s;
#pragma unroll
        for (int i = 0; i < 8; i++) gate[(long)b * 8 + i] = acc[i] * inv;
    }
}

// ---------------------------------------------------------------------------
// Mixture: mix[b][c] = sum_e gate[b][e] * eo[b][e][c]. One block per row.
// ---------------------------------------------------------------------------
__global__ void mixture_kernel(const float* __restrict__ gate, const float* __restrict__ eo,
                               float* __restrict__ mix)
{
    int b = blockIdx.x;
    __shared__ float gs[8];
    if (threadIdx.x < 8) gs[threadIdx.x] = gate[(long)b * 8 + threadIdx.x];
    __syncthreads();

    int c4 = threadIdx.x;  // 256 threads x float4 = 1024 cols
    const float4* eob = reinterpret_cast<const float4*>(eo + (long)b * E_DIM * C_DIM);
    float4 a = make_float4(0.f, 0.f, 0.f, 0.f);
#pragma unroll
    for (int e = 0; e < 8; e++) {
        float4 v = eob[e * (C_DIM / 4) + c4];
        float ge = gs[e];
        a.x += ge * v.x; a.y += ge * v.y; a.z += ge * v.z; a.w += ge * v.w;
    }
    reinterpret_cast<float4*>(mix + (long)b * C_DIM)[c4] = a;
}

// ---------------------------------------------------------------------------
// kernel_launch
// ---------------------------------------------------------------------------
extern "C" void kernel_launch(void* const* d_in, const int* in_sizes, int n_in,
                              void* d_out, int out_size)
{
    const float* x  = (const float*)d_in[0];
    const float* W1 = (const float*)d_in[1];
    const float* b1 = (const float*)d_in[2];
    const float* W2 = (const float*)d_in[3];
    const float* b2 = (const float*)d_in[4];
    const float* Wg = (const float*)d_in[5];
    const float* bg = (const float*)d_in[6];

    // Output layout: mixture [B,C] | gating [B,E] | expert_outputs [B,E,C]
    float* out  = (float*)d_out;
    float* mix  = out;
    float* gate = out + (size_t)B_DIM * C_DIM;
    float* eo   = gate + (size_t)B_DIM * E_DIM;

    float* hbuf = nullptr;
    cudaGetSymbolAddress((void**)&hbuf, g_hbuf);

    cudaFuncSetAttribute(gemm_tf32<true>,  cudaFuncAttributeMaxDynamicSharedMemorySize, SMEM_BYTES);
    cudaFuncSetAttribute(gemm_tf32<false>, cudaFuncAttributeMaxDynamicSharedMemorySize, SMEM_BYTES);

    // 1) gating
    gating_kernel<<<B_DIM / 8, 256>>>(x, Wg, bg, gate);

    // 2) h = relu(x @ W1[e] + b1[e])  -> hbuf [B][E][H]
    //    A = x (lda=D), B = W1[e] (ldb=H), C = hbuf + e*H (ldc=E*H)
    dim3 g1(H_DIM / BN, B_DIM / BM, E_DIM);
    gemm_tf32<true><<<g1, 256, SMEM_BYTES>>>(
        x, W1, b1, hbuf,
        /*K=*/D_DIM, /*lda=*/D_DIM, /*ldb=*/H_DIM, /*ldc=*/E_DIM * H_DIM,
        /*sAe=*/0L, /*sBe=*/(long)D_DIM * H_DIM, /*sBiasE=*/(long)H_DIM, /*sCe=*/(long)H_DIM);

    // 3) eo[:,e,:] = h_e @ W2[e] + b2[e]
    //    A = hbuf + e*H (lda=E*H), B = W2[e] (ldb=C), C = eo + e*C (ldc=E*C)
    dim3 g2(C_DIM / BN, B_DIM / BM, E_DIM);
    gemm_tf32<false><<<g2, 256, SMEM_BYTES>>>(
        hbuf, W2, b2, eo,
        /*K=*/H_DIM, /*lda=*/E_DIM * H_DIM, /*ldb=*/C_DIM, /*ldc=*/E_DIM * C_DIM,
        /*sAe=*/(long)H_DIM, /*sBe=*/(long)H_DIM * C_DIM, /*sBiasE=*/(long)C_DIM, /*sCe=*/(long)C_DIM);

    // 4) mixture
    mixture_kernel<<<B_DIM, 256>>>(gate, eo, mix);
}

// round 9
// speedup vs baseline: 1.2356x; 1.2356x over previous
#include <cuda_runtime.h>
#include <math.h>
#include <stdint.h>

// Problem dims
#define B_DIM 8192
#define D_DIM 1024
#define H_DIM 4096
#define E_DIM 8
#define C_DIM 1024

// GEMM tiling
#define BM 128
#define BN 128
#define BK 32
#define NST 3
#define AS_ST (BK + 4)           // 36 floats
#define BS_ST (BN + 8)           // 136 floats
#define STAGE_A (BM * AS_ST)     // 4608 floats
#define STAGE_B (BK * BS_ST)     // 4352 floats
#define STAGE_F (STAGE_A + STAGE_B)
#define SMEM_BYTES (NST * STAGE_F * 4)   // 107520 bytes

// Scratch (__device__ globals; allocation-free rule)
__device__ float g_hbuf[(size_t)B_DIM * E_DIM * H_DIM];   // 1 GiB: rna(relu(x@W1+b1))
__device__ float g_w1r [(size_t)E_DIM * D_DIM * H_DIM];   // 134 MB: rna(W1)
__device__ float g_w2r [(size_t)E_DIM * H_DIM * C_DIM];   // 134 MB: rna(W2)
__device__ float g_xr  [(size_t)B_DIM * D_DIM];           // 32 MB: rna(x)

// ---------------------------------------------------------------------------
// helpers
// ---------------------------------------------------------------------------
__device__ __forceinline__ float rna_tf32(float f) {
    unsigned u;
    asm("cvt.rna.tf32.f32 %0, %1;" : "=r"(u) : "f"(f));
    return __uint_as_float(u);
}

__device__ __forceinline__ void cp_async16(const float* smem_dst, const float* gsrc) {
    unsigned s = (unsigned)__cvta_generic_to_shared((void*)smem_dst);
    asm volatile("cp.async.cg.shared.global [%0], [%1], 16;" :: "r"(s), "l"(gsrc));
}

__device__ __forceinline__ void mma_tf32(float* c, const unsigned* a, const unsigned* b) {
    asm volatile(
        "mma.sync.aligned.m16n8k8.row.col.f32.tf32.tf32.f32 "
        "{%0,%1,%2,%3}, {%4,%5,%6,%7}, {%8,%9}, {%0,%1,%2,%3};"
        : "+f"(c[0]), "+f"(c[1]), "+f"(c[2]), "+f"(c[3])
        : "r"(a[0]), "r"(a[1]), "r"(a[2]), "r"(a[3]), "r"(b[0]), "r"(b[1]));
}

// ---------------------------------------------------------------------------
// TF32 GEMM (pre-rounded operands): C = op( A @ B + bias )
// A: [M][K] row-major (lda). B: [K][N] row-major (ldb). Per-expert via z.
// 3-stage cp.async pipeline, 1 sync/tile, register fragment double-buffer.
// ---------------------------------------------------------------------------
template <bool RELU_RND>
__global__ void __launch_bounds__(256, 1)
gemm_tf32(const float* __restrict__ A, const float* __restrict__ B,
          const float* __restrict__ bias, float* __restrict__ C,
          int K, int lda, int ldb, int ldc,
          long sAe, long sBe, long sBiasE, long sCe)
{
    extern __shared__ float sm[];

    const int e = blockIdx.z;
    A    += (long)e * sAe;
    B    += (long)e * sBe;
    bias += (long)e * sBiasE;
    C    += (long)e * sCe;

    const int m0 = blockIdx.y * BM;
    const int n0 = blockIdx.x * BN;
    const int tid  = threadIdx.x;
    const int lane = tid & 31;
    const int wid  = tid >> 5;
    const int wm0 = (wid & 1) * 64;   // 2 warps along M
    const int wn0 = (wid >> 1) * 32;  // 4 warps along N
    const int g = lane >> 2, q = lane & 3;

    float acc[4][4][4];
#pragma unroll
    for (int mt = 0; mt < 4; mt++)
#pragma unroll
        for (int nt = 0; nt < 4; nt++)
#pragma unroll
            for (int i = 0; i < 4; i++) acc[mt][nt][i] = 0.f;

    auto load_tile = [&](int kb, int s) {
        float* as = sm + s * STAGE_F;
        float* bs = as + STAGE_A;
#pragma unroll
        for (int i = 0; i < 4; i++) {            // A: 128x32 floats
            int lin = tid + i * 256;
            int row = lin >> 3, k4 = (lin & 7) << 2;
            cp_async16(&as[row * AS_ST + k4], &A[(long)(m0 + row) * lda + kb + k4]);
        }
#pragma unroll
        for (int i = 0; i < 4; i++) {            // B: 32x128 floats
            int lin = tid + i * 256;
            int kr = lin >> 5, n4 = (lin & 31) << 2;
            cp_async16(&bs[kr * BS_ST + n4], &B[(long)(kb + kr) * ldb + n0 + n4]);
        }
        asm volatile("cp.async.commit_group;" ::: "memory");
    };

    // fragment load for k-chunk kk from stage s (no cvt: operands pre-rounded)
    auto load_frag = [&](int kk, int s, unsigned af[4][4], unsigned bf[4][2]) {
        const unsigned* as = (const unsigned*)(sm + s * STAGE_F);
        const unsigned* bs = as + STAGE_A;
        const int k0 = kk * 8;
#pragma unroll
        for (int mt = 0; mt < 4; mt++) {
            int r = wm0 + mt * 16 + g;
            af[mt][0] = as[r * AS_ST + k0 + q];
            af[mt][1] = as[(r + 8) * AS_ST + k0 + q];
            af[mt][2] = as[r * AS_ST + k0 + q + 4];
            af[mt][3] = as[(r + 8) * AS_ST + k0 + q + 4];
        }
#pragma unroll
        for (int nt = 0; nt < 4; nt++) {
            int n = wn0 + nt * 8 + g;
            bf[nt][0] = bs[(k0 + q) * BS_ST + n];
            bf[nt][1] = bs[(k0 + q + 4) * BS_ST + n];
        }
    };

    const int KT = K / BK;   // 32 or 128

    // prologue: 2 stages in flight, stage 0 resident, frags(kk=0) in regs
    load_tile(0, 0);
    load_tile(BK, 1);
    asm volatile("cp.async.wait_group 1;" ::: "memory");
    __syncthreads();

    unsigned a[2][4][4], b[2][4][2];
    load_frag(0, 0, a[0], b[0]);

    for (int kt = 0; kt < KT; kt++) {
        const int cur = kt % NST;
#pragma unroll
        for (int kk = 0; kk < 4; kk++) {
            const int cb = kk & 1, nb = cb ^ 1;
            if (kk == 3) {
                // make stage kt+1 resident, then prefetch its first chunk
                asm volatile("cp.async.wait_group 1;" ::: "memory");
                __syncthreads();
                if (kt + 1 < KT)
                    load_frag(0, (kt + 1) % NST, a[nb], b[nb]);
            } else {
                load_frag(kk + 1, cur, a[nb], b[nb]);
            }
            if (kk == 0) {
                // refill the stage freed at the previous iteration's sync
                if (kt + 2 < KT) load_tile((kt + 2) * BK, (kt + 2) % NST);
                else asm volatile("cp.async.commit_group;" ::: "memory"); // keep count uniform
            }
#pragma unroll
            for (int mt = 0; mt < 4; mt++)
#pragma unroll
                for (int nt = 0; nt < 4; nt++)
                    mma_tf32(acc[mt][nt], a[cb][mt], b[cb][nt]);
        }
    }

    // Epilogue: + bias, optional relu+rna (pre-round h for GEMM2), store
#pragma unroll
    for (int mt = 0; mt < 4; mt++) {
        int r = m0 + wm0 + mt * 16 + g;
#pragma unroll
        for (int nt = 0; nt < 4; nt++) {
            int c = n0 + wn0 + nt * 8 + 2 * q;
            float b0v = bias[c], b1v = bias[c + 1];
            float v00 = acc[mt][nt][0] + b0v;
            float v01 = acc[mt][nt][1] + b1v;
            float v10 = acc[mt][nt][2] + b0v;
            float v11 = acc[mt][nt][3] + b1v;
            if (RELU_RND) {
                v00 = rna_tf32(fmaxf(v00, 0.f)); v01 = rna_tf32(fmaxf(v01, 0.f));
                v10 = rna_tf32(fmaxf(v10, 0.f)); v11 = rna_tf32(fmaxf(v11, 0.f));
            }
            C[(long)r * ldc + c]           = v00;
            C[(long)r * ldc + c + 1]       = v01;
            C[(long)(r + 8) * ldc + c]     = v10;
            C[(long)(r + 8) * ldc + c + 1] = v11;
        }
    }
}

// ---------------------------------------------------------------------------
// Pre-pass: elementwise rna-round copy (n multiple of 1024)
// ---------------------------------------------------------------------------
__global__ void rna_copy(const float* __restrict__ in, float* __restrict__ out)
{
    long i = ((long)blockIdx.x * 256 + threadIdx.x) * 4;
    float4 v = *(const float4*)&in[i];
    v.x = rna_tf32(v.x); v.y = rna_tf32(v.y);
    v.z = rna_tf32(v.z); v.w = rna_tf32(v.w);
    *(float4*)&out[i] = v;
}

// ---------------------------------------------------------------------------
// Gating: softmax(x @ Wg + bg). One warp per row (fp32 exact).
// ---------------------------------------------------------------------------
__global__ void gating_kernel(const float* __restrict__ x, const float* __restrict__ Wg,
                              const float* __restrict__ bg, float* __restrict__ gate)
{
    int warp = threadIdx.x >> 5, lane = threadIdx.x & 31;
    int b = blockIdx.x * 8 + warp;
    const float* xr = x + (long)b * D_DIM;

    float acc[8];
#pragma unroll
    for (int i = 0; i < 8; i++) acc[i] = 0.f;

    for (int d = lane; d < D_DIM; d += 32) {
        float xv = xr[d];
        const float4* w = reinterpret_cast<const float4*>(Wg + (long)d * E_DIM);
        float4 w0 = w[0], w1 = w[1];
        acc[0] += xv * w0.x; acc[1] += xv * w0.y;
        acc[2] += xv * w0.z; acc[3] += xv * w0.w;
        acc[4] += xv * w1.x; acc[5] += xv * w1.y;
        acc[6] += xv * w1.z; acc[7] += xv * w1.w;
    }
#pragma unroll
    for (int off = 16; off > 0; off >>= 1)
#pragma unroll
        for (int i = 0; i < 8; i++)
            acc[i] += __shfl_xor_sync(0xffffffffu, acc[i], off);

    if (lane == 0) {
        float m = -1e30f;
#pragma unroll
        for (int i = 0; i < 8; i++) { acc[i] += bg[i]; m = fmaxf(m, acc[i]); }
        float s = 0.f;
#pragma unroll
        for (int i = 0; i < 8; i++) { acc[i] = expf(acc[i] - m); s += acc[i]; }
        float inv = 1.f / s;
#pragma unroll
        for (int i = 0; i < 8; i++) gate[(long)b * 8 + i] = acc[i] * inv;
    }
}

// ---------------------------------------------------------------------------
// Mixture: mix[b][c] = sum_e gate[b][e] * eo[b][e][c]
// ---------------------------------------------------------------------------
__global__ void mixture_kernel(const float* __restrict__ gate, const float* __restrict__ eo,
                               float* __restrict__ mix)
{
    int b = blockIdx.x;
    __shared__ float gs[8];
    if (threadIdx.x < 8) gs[threadIdx.x] = gate[(long)b * 8 + threadIdx.x];
    __syncthreads();

    int c4 = threadIdx.x;
    const float4* eob = reinterpret_cast<const float4*>(eo + (long)b * E_DIM * C_DIM);
    float4 a = make_float4(0.f, 0.f, 0.f, 0.f);
#pragma unroll
    for (int e = 0; e < 8; e++) {
        float4 v = eob[e * (C_DIM / 4) + c4];
        float ge = gs[e];
        a.x += ge * v.x; a.y += ge * v.y; a.z += ge * v.z; a.w += ge * v.w;
    }
    reinterpret_cast<float4*>(mix + (long)b * C_DIM)[c4] = a;
}

// ---------------------------------------------------------------------------
// kernel_launch
// ---------------------------------------------------------------------------
extern "C" void kernel_launch(void* const* d_in, const int* in_sizes, int n_in,
                              void* d_out, int out_size)
{
    const float* x  = (const float*)d_in[0];
    const float* W1 = (const float*)d_in[1];
    const float* b1 = (const float*)d_in[2];
    const float* W2 = (const float*)d_in[3];
    const float* b2 = (const float*)d_in[4];
    const float* Wg = (const float*)d_in[5];
    const float* bg = (const float*)d_in[6];

    // Output layout: mixture [B,C] | gating [B,E] | expert_outputs [B,E,C]
    float* out  = (float*)d_out;
    float* mix  = out;
    float* gate = out + (size_t)B_DIM * C_DIM;
    float* eo   = gate + (size_t)B_DIM * E_DIM;

    float *hbuf, *w1r, *w2r, *xr;
    cudaGetSymbolAddress((void**)&hbuf, g_hbuf);
    cudaGetSymbolAddress((void**)&w1r,  g_w1r);
    cudaGetSymbolAddress((void**)&w2r,  g_w2r);
    cudaGetSymbolAddress((void**)&xr,   g_xr);

    cudaFuncSetAttribute(gemm_tf32<true>,  cudaFuncAttributeMaxDynamicSharedMemorySize, SMEM_BYTES);
    cudaFuncSetAttribute(gemm_tf32<false>, cudaFuncAttributeMaxDynamicSharedMemorySize, SMEM_BYTES);

    // gating (fp32 exact, independent of everything else)
    gating_kernel<<<B_DIM / 8, 256>>>(x, Wg, bg, gate);

    // pre-round operands to tf32 (removes in-loop CVT from the GEMMs)
    rna_copy<<<((long)B_DIM * D_DIM) / 1024, 256>>>(x, xr);
    rna_copy<<<((long)E_DIM * D_DIM * H_DIM) / 1024, 256>>>(W1, w1r);
    rna_copy<<<((long)E_DIM * H_DIM * C_DIM) / 1024, 256>>>(W2, w2r);

    // GEMM1: h = rna(relu(x @ W1[e] + b1[e])) -> hbuf [B][E][H]
    dim3 g1(H_DIM / BN, B_DIM / BM, E_DIM);
    gemm_tf32<true><<<g1, 256, SMEM_BYTES>>>(
        xr, w1r, b1, hbuf,
        /*K=*/D_DIM, /*lda=*/D_DIM, /*ldb=*/H_DIM, /*ldc=*/E_DIM * H_DIM,
        /*sAe=*/0L, /*sBe=*/(long)D_DIM * H_DIM, /*sBiasE=*/(long)H_DIM, /*sCe=*/(long)H_DIM);

    // GEMM2: eo[:,e,:] = h_e @ W2[e] + b2[e]  (fp32 epilogue, no rounding)
    dim3 g2(C_DIM / BN, B_DIM / BM, E_DIM);
    gemm_tf32<false><<<g2, 256, SMEM_BYTES>>>(
        hbuf, w2r, b2, eo,
        /*K=*/H_DIM, /*lda=*/E_DIM * H_DIM, /*ldb=*/C_DIM, /*ldc=*/E_DIM * C_DIM,
        /*sAe=*/(long)H_DIM, /*sBe=*/(long)H_DIM * C_DIM, /*sBiasE=*/(long)C_DIM, /*sCe=*/(long)C_DIM);

    // mixture
    mixture_kernel<<<B_DIM, 256>>>(gate, eo, mix);
}

// round 10
// speedup vs baseline: 1.9997x; 1.6184x over previous
#include <cuda_runtime.h>
#include <cuda_fp16.h>
#include <math.h>
#include <stdint.h>

// Problem dims
#define B_DIM 8192
#define D_DIM 1024
#define H_DIM 4096
#define E_DIM 8
#define C_DIM 1024

// GEMM tiling (fp16 operands, fp32 accum)
#define BM 128
#define BN 128
#define BK 32
#define NST 3
#define AS_ST 40                         // halves per A row (128x32 + pad) -> conflict-free LDSM
#define BS_ST 136                        // halves per B row (32x128 + pad)
#define A_STAGE_BYTES (BM * AS_ST * 2)   // 10240
#define B_STAGE_BYTES (BK * BS_ST * 2)   // 8704
#define STAGE_BYTES (A_STAGE_BYTES + B_STAGE_BYTES)  // 18944
#define SMEM_BYTES (NST * STAGE_BYTES)   // 56832

// Scratch (__device__ globals; allocation-free rule)
__device__ __half g_hbuf[(size_t)B_DIM * E_DIM * H_DIM];  // 512 MB: relu(x@W1+b1) as fp16
__device__ __half g_w1h [(size_t)E_DIM * D_DIM * H_DIM];  // 64 MB
__device__ __half g_w2h [(size_t)E_DIM * H_DIM * C_DIM];  // 64 MB
__device__ __half g_xh  [(size_t)B_DIM * D_DIM];          // 16 MB

// ---------------------------------------------------------------------------
// helpers
// ---------------------------------------------------------------------------
__device__ __forceinline__ void cp_async16(const void* smem_dst, const void* gsrc) {
    unsigned s = (unsigned)__cvta_generic_to_shared((void*)smem_dst);
    asm volatile("cp.async.cg.shared.global [%0], [%1], 16;" :: "r"(s), "l"(gsrc));
}

__device__ __forceinline__ void ldsm_x4(uint32_t* r, uint32_t addr) {
    asm volatile("ldmatrix.sync.aligned.m8n8.x4.shared.b16 {%0,%1,%2,%3}, [%4];"
                 : "=r"(r[0]), "=r"(r[1]), "=r"(r[2]), "=r"(r[3]) : "r"(addr));
}
__device__ __forceinline__ void ldsm_x4_t(uint32_t* r, uint32_t addr) {
    asm volatile("ldmatrix.sync.aligned.m8n8.x4.trans.shared.b16 {%0,%1,%2,%3}, [%4];"
                 : "=r"(r[0]), "=r"(r[1]), "=r"(r[2]), "=r"(r[3]) : "r"(addr));
}

__device__ __forceinline__ void mma_f16(float* c, const uint32_t* a, const uint32_t* b) {
    asm volatile(
        "mma.sync.aligned.m16n8k16.row.col.f32.f16.f16.f32 "
        "{%0,%1,%2,%3}, {%4,%5,%6,%7}, {%8,%9}, {%0,%1,%2,%3};"
        : "+f"(c[0]), "+f"(c[1]), "+f"(c[2]), "+f"(c[3])
        : "r"(a[0]), "r"(a[1]), "r"(a[2]), "r"(a[3]), "r"(b[0]), "r"(b[1]));
}

// ---------------------------------------------------------------------------
// FP16 GEMM (fp32 accum): C = op( A @ B + bias )
// A: [M][K] half row-major (lda). B: [K][N] half row-major (ldb). Expert via z.
// 3-stage cp.async pipeline, 1 sync/tile, ldmatrix frags, reg double-buffer.
// HOUT: store half with relu (GEMM1 -> hbuf); else fp32 store (GEMM2 -> eo).
// ---------------------------------------------------------------------------
template <bool HOUT>
__global__ void __launch_bounds__(256, 1)
gemm_f16(const __half* __restrict__ A, const __half* __restrict__ B,
         const float* __restrict__ bias, void* __restrict__ Cv,
         int K, int lda, int ldb, int ldc,
         long sAe, long sBe, long sBiasE, long sCe)
{
    extern __shared__ __half sm[];

    const int e = blockIdx.z;
    A    += (long)e * sAe;
    B    += (long)e * sBe;
    bias += (long)e * sBiasE;

    const int m0 = blockIdx.y * BM;
    const int n0 = blockIdx.x * BN;
    const int tid  = threadIdx.x;
    const int lane = tid & 31;
    const int wid  = tid >> 5;
    const int wm0 = (wid & 1) * 64;   // 2 warps along M
    const int wn0 = (wid >> 1) * 32;  // 4 warps along N
    const int g = lane >> 2, q = lane & 3;

    const uint32_t sm_u32 = (uint32_t)__cvta_generic_to_shared(sm);

    // LDSM per-lane address components
    const int aRow = ((lane >> 3) & 1) * 8 + (lane & 7);   // + mt*16 + wm0
    const int aCol = (lane >> 4) * 8;                      // + kk*16
    const int bRow = ((lane >> 3) & 1) * 8 + (lane & 7);   // + kk*16
    const int bCol = (lane >> 4) * 8 + wn0;                // + p*16

    float acc[4][4][4];
#pragma unroll
    for (int mt = 0; mt < 4; mt++)
#pragma unroll
        for (int nt = 0; nt < 4; nt++)
#pragma unroll
            for (int i = 0; i < 4; i++) acc[mt][nt][i] = 0.f;

    auto load_tile = [&](int kb, int s) {
        __half* as = sm + s * (STAGE_BYTES / 2);
        __half* bs = as + A_STAGE_BYTES / 2;
#pragma unroll
        for (int i = 0; i < 2; i++) {            // A: 128 rows x 4 chunks(16B)
            int lin = tid + i * 256;
            int row = lin >> 2, c8 = (lin & 3) << 3;
            cp_async16(&as[row * AS_ST + c8], &A[(long)(m0 + row) * lda + kb + c8]);
        }
#pragma unroll
        for (int i = 0; i < 2; i++) {            // B: 32 rows x 16 chunks(16B)
            int lin = tid + i * 256;
            int kr = lin >> 4, c8 = (lin & 15) << 3;
            cp_async16(&bs[kr * BS_ST + c8], &B[(long)(kb + kr) * ldb + n0 + c8]);
        }
        asm volatile("cp.async.commit_group;" ::: "memory");
    };

    // fragment load for k16-chunk kk from stage s via ldmatrix
    auto load_frag = [&](int kk, int s, uint32_t af[4][4], uint32_t bf[4][2]) {
        uint32_t sa = sm_u32 + s * STAGE_BYTES;
        uint32_t sb = sa + A_STAGE_BYTES;
#pragma unroll
        for (int mt = 0; mt < 4; mt++)
            ldsm_x4(af[mt], sa + ((wm0 + mt * 16 + aRow) * AS_ST + kk * 16 + aCol) * 2);
#pragma unroll
        for (int p = 0; p < 2; p++) {
            uint32_t r[4];
            ldsm_x4_t(r, sb + ((kk * 16 + bRow) * BS_ST + bCol + p * 16) * 2);
            bf[2 * p][0] = r[0]; bf[2 * p][1] = r[1];
            bf[2 * p + 1][0] = r[2]; bf[2 * p + 1][1] = r[3];
        }
    };

    const int KT = K / BK;   // 32 (GEMM1) or 128 (GEMM2)

    // prologue
    load_tile(0, 0);
    load_tile(BK, 1);
    asm volatile("cp.async.wait_group 1;" ::: "memory");
    __syncthreads();

    uint32_t a[2][4][4], b[2][4][2];
    load_frag(0, 0, a[0], b[0]);

    for (int kt = 0; kt < KT; kt++) {
        const int cur = kt % NST;
#pragma unroll
        for (int kk = 0; kk < 2; kk++) {         // two k16 chunks per BK=32 stage
            const int cb = kk & 1, nb = cb ^ 1;
            if (kk == 1) {
                asm volatile("cp.async.wait_group 1;" ::: "memory");
                __syncthreads();
                if (kt + 1 < KT)
                    load_frag(0, (kt + 1) % NST, a[nb], b[nb]);
            } else {
                load_frag(1, cur, a[nb], b[nb]);
                if (kt + 2 < KT) load_tile((kt + 2) * BK, (kt + 2) % NST);
                else asm volatile("cp.async.commit_group;" ::: "memory");
            }
#pragma unroll
            for (int mt = 0; mt < 4; mt++)
#pragma unroll
                for (int nt = 0; nt < 4; nt++)
                    mma_f16(acc[mt][nt], a[cb][mt], b[cb][nt]);
        }
    }

    // Epilogue
#pragma unroll
    for (int mt = 0; mt < 4; mt++) {
        int r = m0 + wm0 + mt * 16 + g;
#pragma unroll
        for (int nt = 0; nt < 4; nt++) {
            int c = n0 + wn0 + nt * 8 + 2 * q;
            float b0v = bias[c], b1v = bias[c + 1];
            float v00 = acc[mt][nt][0] + b0v;
            float v01 = acc[mt][nt][1] + b1v;
            float v10 = acc[mt][nt][2] + b0v;
            float v11 = acc[mt][nt][3] + b1v;
            if (HOUT) {
                __half* C = (__half*)Cv + (long)e * sCe;
                __half2 h0 = __floats2half2_rn(fmaxf(v00, 0.f), fmaxf(v01, 0.f));
                __half2 h1 = __floats2half2_rn(fmaxf(v10, 0.f), fmaxf(v11, 0.f));
                *(__half2*)&C[(long)r * ldc + c]       = h0;
                *(__half2*)&C[(long)(r + 8) * ldc + c] = h1;
            } else {
                float* C = (float*)Cv + (long)e * sCe;
                C[(long)r * ldc + c]           = v00;
                C[(long)r * ldc + c + 1]       = v01;
                C[(long)(r + 8) * ldc + c]     = v10;
                C[(long)(r + 8) * ldc + c + 1] = v11;
            }
        }
    }
}

// ---------------------------------------------------------------------------
// Pre-pass: fp32 -> fp16 (RNE), n multiple of 1024
// ---------------------------------------------------------------------------
__global__ void f2h_copy(const float* __restrict__ in, __half* __restrict__ out)
{
    long i = ((long)blockIdx.x * 256 + threadIdx.x) * 4;
    float4 v = *(const float4*)&in[i];
    __half2 h0 = __floats2half2_rn(v.x, v.y);
    __half2 h1 = __floats2half2_rn(v.z, v.w);
    uint2 u;
    u.x = *reinterpret_cast<unsigned*>(&h0);
    u.y = *reinterpret_cast<unsigned*>(&h1);
    *(uint2*)(out + i) = u;
}

// ---------------------------------------------------------------------------
// Gating: softmax(x @ Wg + bg). One warp per row (fp32 exact).
// ---------------------------------------------------------------------------
__global__ void gating_kernel(const float* __restrict__ x, const float* __restrict__ Wg,
                              const float* __restrict__ bg, float* __restrict__ gate)
{
    int warp = threadIdx.x >> 5, lane = threadIdx.x & 31;
    int b = blockIdx.x * 8 + warp;
    const float* xr = x + (long)b * D_DIM;

    float acc[8];
#pragma unroll
    for (int i = 0; i < 8; i++) acc[i] = 0.f;

    for (int d = lane; d < D_DIM; d += 32) {
        float xv = xr[d];
        const float4* w = reinterpret_cast<const float4*>(Wg + (long)d * E_DIM);
        float4 w0 = w[0], w1 = w[1];
        acc[0] += xv * w0.x; acc[1] += xv * w0.y;
        acc[2] += xv * w0.z; acc[3] += xv * w0.w;
        acc[4] += xv * w1.x; acc[5] += xv * w1.y;
        acc[6] += xv * w1.z; acc[7] += xv * w1.w;
    }
#pragma unroll
    for (int off = 16; off > 0; off >>= 1)
#pragma unroll
        for (int i = 0; i < 8; i++)
            acc[i] += __shfl_xor_sync(0xffffffffu, acc[i], off);

    if (lane == 0) {
        float m = -1e30f;
#pragma unroll
        for (int i = 0; i < 8; i++) { acc[i] += bg[i]; m = fmaxf(m, acc[i]); }
        float s = 0.f;
#pragma unroll
        for (int i = 0; i < 8; i++) { acc[i] = expf(acc[i] - m); s += acc[i]; }
        float inv = 1.f / s;
#pragma unroll
        for (int i = 0; i < 8; i++) gate[(long)b * 8 + i] = acc[i] * inv;
    }
}

// ---------------------------------------------------------------------------
// Mixture: mix[b][c] = sum_e gate[b][e] * eo[b][e][c]
// ---------------------------------------------------------------------------
__global__ void mixture_kernel(const float* __restrict__ gate, const float* __restrict__ eo,
                               float* __restrict__ mix)
{
    int b = blockIdx.x;
    __shared__ float gs[8];
    if (threadIdx.x < 8) gs[threadIdx.x] = gate[(long)b * 8 + threadIdx.x];
    __syncthreads();

    int c4 = threadIdx.x;
    const float4* eob = reinterpret_cast<const float4*>(eo + (long)b * E_DIM * C_DIM);
    float4 a = make_float4(0.f, 0.f, 0.f, 0.f);
#pragma unroll
    for (int e = 0; e < 8; e++) {
        float4 v = eob[e * (C_DIM / 4) + c4];
        float ge = gs[e];
        a.x += ge * v.x; a.y += ge * v.y; a.z += ge * v.z; a.w += ge * v.w;
    }
    reinterpret_cast<float4*>(mix + (long)b * C_DIM)[c4] = a;
}

// ---------------------------------------------------------------------------
// kernel_launch
// ---------------------------------------------------------------------------
extern "C" void kernel_launch(void* const* d_in, const int* in_sizes, int n_in,
                              void* d_out, int out_size)
{
    const float* x  = (const float*)d_in[0];
    const float* W1 = (const float*)d_in[1];
    const float* b1 = (const float*)d_in[2];
    const float* W2 = (const float*)d_in[3];
    const float* b2 = (const float*)d_in[4];
    const float* Wg = (const float*)d_in[5];
    const float* bg = (const float*)d_in[6];

    // Output layout: mixture [B,C] | gating [B,E] | expert_outputs [B,E,C]
    float* out  = (float*)d_out;
    float* mix  = out;
    float* gate = out + (size_t)B_DIM * C_DIM;
    float* eo   = gate + (size_t)B_DIM * E_DIM;

    __half *hbuf, *w1h, *w2h, *xh;
    cudaGetSymbolAddress((void**)&hbuf, g_hbuf);
    cudaGetSymbolAddress((void**)&w1h,  g_w1h);
    cudaGetSymbolAddress((void**)&w2h,  g_w2h);
    cudaGetSymbolAddress((void**)&xh,   g_xh);

    cudaFuncSetAttribute(gemm_f16<true>,  cudaFuncAttributeMaxDynamicSharedMemorySize, SMEM_BYTES);
    cudaFuncSetAttribute(gemm_f16<false>, cudaFuncAttributeMaxDynamicSharedMemorySize, SMEM_BYTES);

    // gating (fp32 exact, independent)
    gating_kernel<<<B_DIM / 8, 256>>>(x, Wg, bg, gate);

    // pre-convert operands to fp16
    f2h_copy<<<((long)B_DIM * D_DIM) / 1024, 256>>>(x, xh);
    f2h_copy<<<((long)E_DIM * D_DIM * H_DIM) / 1024, 256>>>(W1, w1h);
    f2h_copy<<<((long)E_DIM * H_DIM * C_DIM) / 1024, 256>>>(W2, w2h);

    // GEMM1: hbuf = fp16(relu(x @ W1[e] + b1[e]))  [B][E][H]
    dim3 g1(H_DIM / BN, B_DIM / BM, E_DIM);
    gemm_f16<true><<<g1, 256, SMEM_BYTES>>>(
        xh, w1h, b1, hbuf,
        /*K=*/D_DIM, /*lda=*/D_DIM, /*ldb=*/H_DIM, /*ldc=*/E_DIM * H_DIM,
        /*sAe=*/0L, /*sBe=*/(long)D_DIM * H_DIM, /*sBiasE=*/(long)H_DIM, /*sCe=*/(long)H_DIM);

    // GEMM2: eo[:,e,:] = h_e @ W2[e] + b2[e]  (fp32 store)
    dim3 g2(C_DIM / BN, B_DIM / BM, E_DIM);
    gemm_f16<false><<<g2, 256, SMEM_BYTES>>>(
        hbuf, w2h, b2, eo,
        /*K=*/H_DIM, /*lda=*/E_DIM * H_DIM, /*ldb=*/C_DIM, /*ldc=*/E_DIM * C_DIM,
        /*sAe=*/(long)H_DIM, /*sBe=*/(long)H_DIM * C_DIM, /*sBiasE=*/(long)C_DIM, /*sCe=*/(long)C_DIM);

    // mixture
    mixture_kernel<<<B_DIM, 256>>>(gate, eo, mix);
}

// round 11
// speedup vs baseline: 2.8424x; 1.4214x over previous
#include <cuda_runtime.h>
#include <cuda_fp16.h>
#include <math.h>
#include <stdint.h>

// Problem dims
#define B_DIM 8192
#define D_DIM 1024
#define H_DIM 4096
#define E_DIM 8
#define C_DIM 1024

// GEMM tiling (fp16 operands, fp32 accum)
#define BM 128
#define BN 256
#define BK 32
#define NST 3
#define AS_ST 40                         // halves per A row -> conflict-free LDSM
#define BS_ST 264                        // halves per B row (256 + 8 pad)
#define A_STAGE_BYTES (BM * AS_ST * 2)   // 10240
#define B_STAGE_BYTES (BK * BS_ST * 2)   // 16896
#define STAGE_BYTES (A_STAGE_BYTES + B_STAGE_BYTES)  // 27136
#define SMEM_BYTES (NST * STAGE_BYTES)   // 81408

// Scratch (__device__ globals; allocation-free rule)
__device__ __half g_hbuf[(size_t)B_DIM * E_DIM * H_DIM];  // 512 MB: relu(x@W1+b1) fp16
__device__ __half g_w1h [(size_t)E_DIM * D_DIM * H_DIM];  // 64 MB
__device__ __half g_w2h [(size_t)E_DIM * H_DIM * C_DIM];  // 64 MB
__device__ __half g_xh  [(size_t)B_DIM * D_DIM];          // 16 MB

// ---------------------------------------------------------------------------
// helpers
// ---------------------------------------------------------------------------
__device__ __forceinline__ void cp_async16(const void* smem_dst, const void* gsrc) {
    unsigned s = (unsigned)__cvta_generic_to_shared((void*)smem_dst);
    asm volatile("cp.async.cg.shared.global [%0], [%1], 16;" :: "r"(s), "l"(gsrc));
}

__device__ __forceinline__ void ldsm_x4(uint32_t* r, uint32_t addr) {
    asm volatile("ldmatrix.sync.aligned.m8n8.x4.shared.b16 {%0,%1,%2,%3}, [%4];"
                 : "=r"(r[0]), "=r"(r[1]), "=r"(r[2]), "=r"(r[3]) : "r"(addr));
}
__device__ __forceinline__ void ldsm_x4_t(uint32_t* r, uint32_t addr) {
    asm volatile("ldmatrix.sync.aligned.m8n8.x4.trans.shared.b16 {%0,%1,%2,%3}, [%4];"
                 : "=r"(r[0]), "=r"(r[1]), "=r"(r[2]), "=r"(r[3]) : "r"(addr));
}

__device__ __forceinline__ void mma_f16(float* c, const uint32_t* a, const uint32_t* b) {
    asm volatile(
        "mma.sync.aligned.m16n8k16.row.col.f32.f16.f16.f32 "
        "{%0,%1,%2,%3}, {%4,%5,%6,%7}, {%8,%9}, {%0,%1,%2,%3};"
        : "+f"(c[0]), "+f"(c[1]), "+f"(c[2]), "+f"(c[3])
        : "r"(a[0]), "r"(a[1]), "r"(a[2]), "r"(a[3]), "r"(b[0]), "r"(b[1]));
}

// ---------------------------------------------------------------------------
// FP16 GEMM (fp32 accum): C = op( A @ B + bias )
// A: [M][K] half row-major (lda). B: [K][N] half row-major (ldb). Expert via z.
// CTA tile 128x256, 8 warps of 64x64. 3-stage cp.async, 1 sync/tile,
// ldmatrix frags, register double-buffer.
// HOUT: store half with relu (GEMM1 -> hbuf); else fp32 store (GEMM2 -> eo).
// ---------------------------------------------------------------------------
template <bool HOUT>
__global__ void __launch_bounds__(256, 1)
gemm_f16(const __half* __restrict__ A, const __half* __restrict__ B,
         const float* __restrict__ bias, void* __restrict__ Cv,
         int K, int lda, int ldb, int ldc,
         long sAe, long sBe, long sBiasE, long sCe)
{
    extern __shared__ __half sm[];

    const int e = blockIdx.z;
    A    += (long)e * sAe;
    B    += (long)e * sBe;
    bias += (long)e * sBiasE;

    const int m0 = blockIdx.y * BM;
    const int n0 = blockIdx.x * BN;
    const int tid  = threadIdx.x;
    const int lane = tid & 31;
    const int wid  = tid >> 5;
    const int wm0 = (wid & 1) * 64;   // 2 warps along M
    const int wn0 = (wid >> 1) * 64;  // 4 warps along N
    const int g = lane >> 2, q = lane & 3;

    const uint32_t sm_u32 = (uint32_t)__cvta_generic_to_shared(sm);

    // LDSM per-lane address components
    const int aRow = ((lane >> 3) & 1) * 8 + (lane & 7);   // + mt*16 + wm0
    const int aCol = (lane >> 4) * 8;                      // + kk*16
    const int bRow = ((lane >> 3) & 1) * 8 + (lane & 7);   // + kk*16
    const int bCol = (lane >> 4) * 8 + wn0;                // + p*16

    float acc[4][8][4];
#pragma unroll
    for (int mt = 0; mt < 4; mt++)
#pragma unroll
        for (int nt = 0; nt < 8; nt++)
#pragma unroll
            for (int i = 0; i < 4; i++) acc[mt][nt][i] = 0.f;

    auto load_tile = [&](int kb, int s) {
        __half* as = sm + s * (STAGE_BYTES / 2);
        __half* bs = as + A_STAGE_BYTES / 2;
#pragma unroll
        for (int i = 0; i < 2; i++) {            // A: 128 rows x 4 chunks(16B)
            int lin = tid + i * 256;
            int row = lin >> 2, c8 = (lin & 3) << 3;
            cp_async16(&as[row * AS_ST + c8], &A[(long)(m0 + row) * lda + kb + c8]);
        }
#pragma unroll
        for (int i = 0; i < 4; i++) {            // B: 32 rows x 32 chunks(16B)
            int lin = tid + i * 256;
            int kr = lin >> 5, c8 = (lin & 31) << 3;
            cp_async16(&bs[kr * BS_ST + c8], &B[(long)(kb + kr) * ldb + n0 + c8]);
        }
        asm volatile("cp.async.commit_group;" ::: "memory");
    };

    // fragment load for k16-chunk kk from stage s via ldmatrix
    auto load_frag = [&](int kk, int s, uint32_t af[4][4], uint32_t bf[8][2]) {
        uint32_t sa = sm_u32 + s * STAGE_BYTES;
        uint32_t sb = sa + A_STAGE_BYTES;
#pragma unroll
        for (int mt = 0; mt < 4; mt++)
            ldsm_x4(af[mt], sa + ((wm0 + mt * 16 + aRow) * AS_ST + kk * 16 + aCol) * 2);
#pragma unroll
        for (int p = 0; p < 4; p++) {
            uint32_t r[4];
            ldsm_x4_t(r, sb + ((kk * 16 + bRow) * BS_ST + bCol + p * 16) * 2);
            bf[2 * p][0] = r[0]; bf[2 * p][1] = r[1];
            bf[2 * p + 1][0] = r[2]; bf[2 * p + 1][1] = r[3];
        }
    };

    const int KT = K / BK;   // 32 (GEMM1) or 128 (GEMM2)

    // prologue
    load_tile(0, 0);
    load_tile(BK, 1);
    asm volatile("cp.async.wait_group 1;" ::: "memory");
    __syncthreads();

    uint32_t a[2][4][4], b[2][8][2];
    load_frag(0, 0, a[0], b[0]);

    for (int kt = 0; kt < KT; kt++) {
        const int cur = kt % NST;
#pragma unroll
        for (int kk = 0; kk < 2; kk++) {         // two k16 chunks per BK=32 stage
            const int cb = kk & 1, nb = cb ^ 1;
            if (kk == 1) {
                asm volatile("cp.async.wait_group 1;" ::: "memory");
                __syncthreads();
                if (kt + 1 < KT)
                    load_frag(0, (kt + 1) % NST, a[nb], b[nb]);
            } else {
                load_frag(1, cur, a[nb], b[nb]);
                if (kt + 2 < KT) load_tile((kt + 2) * BK, (kt + 2) % NST);
                else asm volatile("cp.async.commit_group;" ::: "memory");
            }
#pragma unroll
            for (int mt = 0; mt < 4; mt++)
#pragma unroll
                for (int nt = 0; nt < 8; nt++)
                    mma_f16(acc[mt][nt], a[cb][mt], b[cb][nt]);
        }
    }

    // Epilogue
#pragma unroll
    for (int mt = 0; mt < 4; mt++) {
        int r = m0 + wm0 + mt * 16 + g;
#pragma unroll
        for (int nt = 0; nt < 8; nt++) {
            int c = n0 + wn0 + nt * 8 + 2 * q;
            float b0v = bias[c], b1v = bias[c + 1];
            float v00 = acc[mt][nt][0] + b0v;
            float v01 = acc[mt][nt][1] + b1v;
            float v10 = acc[mt][nt][2] + b0v;
            float v11 = acc[mt][nt][3] + b1v;
            if (HOUT) {
                __half* C = (__half*)Cv + (long)e * sCe;
                __half2 h0 = __floats2half2_rn(fmaxf(v00, 0.f), fmaxf(v01, 0.f));
                __half2 h1 = __floats2half2_rn(fmaxf(v10, 0.f), fmaxf(v11, 0.f));
                *(__half2*)&C[(long)r * ldc + c]       = h0;
                *(__half2*)&C[(long)(r + 8) * ldc + c] = h1;
            } else {
                float* C = (float*)Cv + (long)e * sCe;
                C[(long)r * ldc + c]           = v00;
                C[(long)r * ldc + c + 1]       = v01;
                C[(long)(r + 8) * ldc + c]     = v10;
                C[(long)(r + 8) * ldc + c + 1] = v11;
            }
        }
    }
}

// ---------------------------------------------------------------------------
// Pre-pass: fp32 -> fp16 (RNE), n multiple of 1024
// ---------------------------------------------------------------------------
__global__ void f2h_copy(const float* __restrict__ in, __half* __restrict__ out)
{
    long i = ((long)blockIdx.x * 256 + threadIdx.x) * 4;
    float4 v = *(const float4*)&in[i];
    __half2 h0 = __floats2half2_rn(v.x, v.y);
    __half2 h1 = __floats2half2_rn(v.z, v.w);
    uint2 u;
    u.x = *reinterpret_cast<unsigned*>(&h0);
    u.y = *reinterpret_cast<unsigned*>(&h1);
    *(uint2*)(out + i) = u;
}

// ---------------------------------------------------------------------------
// Gating: softmax(x @ Wg + bg). One warp per row (fp32 exact).
// ---------------------------------------------------------------------------
__global__ void gating_kernel(const float* __restrict__ x, const float* __restrict__ Wg,
                              const float* __restrict__ bg, float* __restrict__ gate)
{
    int warp = threadIdx.x >> 5, lane = threadIdx.x & 31;
    int b = blockIdx.x * 8 + warp;
    const float* xr = x + (long)b * D_DIM;

    float acc[8];
#pragma unroll
    for (int i = 0; i < 8; i++) acc[i] = 0.f;

    for (int d = lane; d < D_DIM; d += 32) {
        float xv = xr[d];
        const float4* w = reinterpret_cast<const float4*>(Wg + (long)d * E_DIM);
        float4 w0 = w[0], w1 = w[1];
        acc[0] += xv * w0.x; acc[1] += xv * w0.y;
        acc[2] += xv * w0.z; acc[3] += xv * w0.w;
        acc[4] += xv * w1.x; acc[5] += xv * w1.y;
        acc[6] += xv * w1.z; acc[7] += xv * w1.w;
    }
#pragma unroll
    for (int off = 16; off > 0; off >>= 1)
#pragma unroll
        for (int i = 0; i < 8; i++)
            acc[i] += __shfl_xor_sync(0xffffffffu, acc[i], off);

    if (lane == 0) {
        float m = -1e30f;
#pragma unroll
        for (int i = 0; i < 8; i++) { acc[i] += bg[i]; m = fmaxf(m, acc[i]); }
        float s = 0.f;
#pragma unroll
        for (int i = 0; i < 8; i++) { acc[i] = expf(acc[i] - m); s += acc[i]; }
        float inv = 1.f / s;
#pragma unroll
        for (int i = 0; i < 8; i++) gate[(long)b * 8 + i] = acc[i] * inv;
    }
}

// ---------------------------------------------------------------------------
// Mixture: mix[b][c] = sum_e gate[b][e] * eo[b][e][c]
// ---------------------------------------------------------------------------
__global__ void mixture_kernel(const float* __restrict__ gate, const float* __restrict__ eo,
                               float* __restrict__ mix)
{
    int b = blockIdx.x;
    __shared__ float gs[8];
    if (threadIdx.x < 8) gs[threadIdx.x] = gate[(long)b * 8 + threadIdx.x];
    __syncthreads();

    int c4 = threadIdx.x;
    const float4* eob = reinterpret_cast<const float4*>(eo + (long)b * E_DIM * C_DIM);
    float4 a = make_float4(0.f, 0.f, 0.f, 0.f);
#pragma unroll
    for (int e = 0; e < 8; e++) {
        float4 v = eob[e * (C_DIM / 4) + c4];
        float ge = gs[e];
        a.x += ge * v.x; a.y += ge * v.y; a.z += ge * v.z; a.w += ge * v.w;
    }
    reinterpret_cast<float4*>(mix + (long)b * C_DIM)[c4] = a;
}

// ---------------------------------------------------------------------------
// kernel_launch
// ---------------------------------------------------------------------------
extern "C" void kernel_launch(void* const* d_in, const int* in_sizes, int n_in,
                              void* d_out, int out_size)
{
    const float* x  = (const float*)d_in[0];
    const float* W1 = (const float*)d_in[1];
    const float* b1 = (const float*)d_in[2];
    const float* W2 = (const float*)d_in[3];
    const float* b2 = (const float*)d_in[4];
    const float* Wg = (const float*)d_in[5];
    const float* bg = (const float*)d_in[6];

    // Output layout: mixture [B,C] | gating [B,E] | expert_outputs [B,E,C]
    float* out  = (float*)d_out;
    float* mix  = out;
    float* gate = out + (size_t)B_DIM * C_DIM;
    float* eo   = gate + (size_t)B_DIM * E_DIM;

    __half *hbuf, *w1h, *w2h, *xh;
    cudaGetSymbolAddress((void**)&hbuf, g_hbuf);
    cudaGetSymbolAddress((void**)&w1h,  g_w1h);
    cudaGetSymbolAddress((void**)&w2h,  g_w2h);
    cudaGetSymbolAddress((void**)&xh,   g_xh);

    cudaFuncSetAttribute(gemm_f16<true>,  cudaFuncAttributeMaxDynamicSharedMemorySize, SMEM_BYTES);
    cudaFuncSetAttribute(gemm_f16<false>, cudaFuncAttributeMaxDynamicSharedMemorySize, SMEM_BYTES);

    // gating (fp32 exact, independent)
    gating_kernel<<<B_DIM / 8, 256>>>(x, Wg, bg, gate);

    // pre-convert operands to fp16
    f2h_copy<<<((long)B_DIM * D_DIM) / 1024, 256>>>(x, xh);
    f2h_copy<<<((long)E_DIM * D_DIM * H_DIM) / 1024, 256>>>(W1, w1h);
    f2h_copy<<<((long)E_DIM * H_DIM * C_DIM) / 1024, 256>>>(W2, w2h);

    // GEMM1: hbuf = fp16(relu(x @ W1[e] + b1[e]))  [B][E][H]
    dim3 g1(H_DIM / BN, B_DIM / BM, E_DIM);
    gemm_f16<true><<<g1, 256, SMEM_BYTES>>>(
        xh, w1h, b1, hbuf,
        /*K=*/D_DIM, /*lda=*/D_DIM, /*ldb=*/H_DIM, /*ldc=*/E_DIM * H_DIM,
        /*sAe=*/0L, /*sBe=*/(long)D_DIM * H_DIM, /*sBiasE=*/(long)H_DIM, /*sCe=*/(long)H_DIM);

    // GEMM2: eo[:,e,:] = h_e @ W2[e] + b2[e]  (fp32 store)
    dim3 g2(C_DIM / BN, B_DIM / BM, E_DIM);
    gemm_f16<false><<<g2, 256, SMEM_BYTES>>>(
        hbuf, w2h, b2, eo,
        /*K=*/H_DIM, /*lda=*/E_DIM * H_DIM, /*ldb=*/C_DIM, /*ldc=*/E_DIM * C_DIM,
        /*sAe=*/(long)H_DIM, /*sBe=*/(long)H_DIM * C_DIM, /*sBiasE=*/(long)C_DIM, /*sCe=*/(long)C_DIM);

    // mixture
    mixture_kernel<<<B_DIM, 256>>>(gate, eo, mix);
}